// round 16
// baseline (speedup 1.0000x reference)
#include <cuda_runtime.h>

typedef unsigned long long u64;

#define BETA 0.95f
#define THRV 1.0f
#define KC   512              // fc1: two 512-halves folded; K=512 stays pure chain

static const int T_STEPS = 10;
static const int MAXB = 16384, MAXH = 512, MAXD = 1024;

// ---- persistent state (device globals; no runtime allocation allowed) ----
__device__ float g_cur1[MAXB * MAXH];   // fc1(x), computed once per launch
__device__ float g_m1[MAXB * MAXH];
__device__ float g_m2[MAXB * MAXH];
__device__ float g_m3[MAXB * MAXD];
__device__ float g_s1[MAXB * MAXH];
__device__ float g_s2[MAXB * MAXH];

// ---- f32x2 packed math (lane-wise identical rounding to scalar ops) ----
__device__ __forceinline__ float2 upk2(u64 v) {
    float2 f;
    asm("mov.b64 {%0, %1}, %2;" : "=f"(f.x), "=f"(f.y) : "l"(v));
    return f;
}
__device__ __forceinline__ u64 pk2(float x, float y) {
    u64 r;
    asm("mov.b64 %0, {%1, %2};" : "=l"(r) : "f"(x), "f"(y));
    return r;
}
__device__ __forceinline__ void ffma2(u64& d, u64 a, u64 b) {
    asm("fma.rn.f32x2 %0, %1, %2, %0;" : "+l"(d) : "l"(a), "l"(b));
}
__device__ __forceinline__ void fadd2(u64& d, u64 a) {
    asm("add.rn.f32x2 %0, %0, %1;" : "+l"(d) : "l"(a));
}

// LIF update, NO FMA contraction: m' = rn(rn(rn(beta*m) + cur) - reset)
__device__ __forceinline__ void lif_step(float& m, float cur, float& s) {
    float reset = (m > THRV) ? THRV : 0.0f;   // reset uses PREVIOUS mem
    float t0 = __fmul_rn(BETA, m);
    float t1 = __fadd_rn(t0, cur);
    m = __fsub_rn(t1, reset);
    s = (m > THRV) ? 1.0f : 0.0f;
}

// ============================================================================
// Fused GEMM:  C[M,N] = A[M,K] @ W[N,K]^T (+bias) -> epilogue per MODE
//   MODE 0: write cur     MODE 1: LIF -> Mst,Sout    MODE 2: LIF -> Oacc
// Tile BM=128, BN=128, BK=16, 256 threads.
// Warp grid 4(m) x 2(n): each warp covers 32 rows x 64 cols
//   -> unique LDS bytes/warp-k = 8*32 + 4*64 = 512B (25% less crossbar).
// Lane: tx=lane&7 -> 8 contiguous cols; ty=lane>>3 -> 8-row group.
// Per-thread 8 rows x 8 cols as 4 f32x2 col-pair lanes; each lane is bitwise
// an ascending-k scalar FMA chain; KC=512 fold (FOLD) reproduces reference.
// Double-buffered smem (48KB), ONE __syncthreads per 16-k stage.
// ============================================================================
template<int MODE, bool FOLD>
__global__ __launch_bounds__(256, FOLD ? 1 : 2)
void gemm_lif(const float* __restrict__ A, const float* __restrict__ W,
              const float* __restrict__ bias,
              float* __restrict__ Ccur,
              float* __restrict__ Mst,
              float* __restrict__ Sout,
              float* __restrict__ Oacc,
              float outScale,
              int M, int N, int K)
{
    __shared__ __align__(16) u64   As2[2][16][128];  // [buf][k][row] = (a,a) dup
    __shared__ __align__(16) float Bs [2][16][128];  // [buf][k][col]

    const int tid    = threadIdx.x;
    const int lane   = tid & 31;
    const int wid    = tid >> 5;
    const int warp_m = wid & 3;        // 0..3 -> 32-row band
    const int warp_n = wid >> 2;       // 0..1 -> 64-col band
    const int tx     = lane & 7;       // 8 contiguous cols at 8*tx
    const int ty     = lane >> 3;      // 0..3 -> 8-row group

    const int rowb = 32 * warp_m + 8 * ty;       // smem row base
    const int colb = 64 * warp_n + 8 * tx;       // smem col base

    const int bm = blockIdx.y * 128;
    const int bn = blockIdx.x * 128;

    const int lr = tid >> 1;          // 0..127 (one A row / one B col)
    const int lk = (tid & 1) << 3;    // 0 or 8

    const float* Ag = A + (size_t)(bm + lr) * K + lk;
    const float* Wg = W + (size_t)(bn + lr) * K + lk;

    u64 acc[8][4];                    // [row r][colpair jp]
    u64 accT[8][4];                   // folded total (FOLD only)
    #pragma unroll
    for (int r = 0; r < 8; r++)
        #pragma unroll
        for (int j = 0; j < 4; j++) { acc[r][j] = 0ull; accT[r][j] = 0ull; }

    // prefetch + store stage 0
    float4 a0 = *(const float4*)(Ag + 0);
    float4 a1 = *(const float4*)(Ag + 4);
    float4 w0 = *(const float4*)(Wg + 0);
    float4 w1 = *(const float4*)(Wg + 4);
    {
        As2[0][lk+0][lr] = pk2(a0.x, a0.x);
        As2[0][lk+1][lr] = pk2(a0.y, a0.y);
        As2[0][lk+2][lr] = pk2(a0.z, a0.z);
        As2[0][lk+3][lr] = pk2(a0.w, a0.w);
        As2[0][lk+4][lr] = pk2(a1.x, a1.x);
        As2[0][lk+5][lr] = pk2(a1.y, a1.y);
        As2[0][lk+6][lr] = pk2(a1.z, a1.z);
        As2[0][lk+7][lr] = pk2(a1.w, a1.w);
        Bs [0][lk+0][lr] = w0.x;
        Bs [0][lk+1][lr] = w0.y;
        Bs [0][lk+2][lr] = w0.z;
        Bs [0][lk+3][lr] = w0.w;
        Bs [0][lk+4][lr] = w1.x;
        Bs [0][lk+5][lr] = w1.y;
        Bs [0][lk+6][lr] = w1.z;
        Bs [0][lk+7][lr] = w1.w;
    }

    const int nT = K >> 4;
    for (int t = 0; t < nT; t++) {
        const int cur = t & 1;
        __syncthreads();              // stage t visible; stage t-1 compute done

        const bool more = (t + 1 < nT);
        if (more) {
            const float* Ap = Ag + (t + 1) * 16;
            const float* Wp = Wg + (t + 1) * 16;
            a0 = *(const float4*)(Ap + 0);
            a1 = *(const float4*)(Ap + 4);
            w0 = *(const float4*)(Wp + 0);
            w1 = *(const float4*)(Wp + 4);
        }

        #pragma unroll
        for (int k = 0; k < 16; k++) {
            ulonglong2 ap0 = *(const ulonglong2*)&As2[cur][k][rowb + 0];
            ulonglong2 ap1 = *(const ulonglong2*)&As2[cur][k][rowb + 2];
            ulonglong2 ap2 = *(const ulonglong2*)&As2[cur][k][rowb + 4];
            ulonglong2 ap3 = *(const ulonglong2*)&As2[cur][k][rowb + 6];
            u64 ar[8] = { ap0.x, ap0.y, ap1.x, ap1.y,
                          ap2.x, ap2.y, ap3.x, ap3.y };
            ulonglong2 bp0 = *(const ulonglong2*)&Bs[cur][k][colb + 0];
            ulonglong2 bp1 = *(const ulonglong2*)&Bs[cur][k][colb + 4];
            u64 bp[4] = { bp0.x, bp0.y, bp1.x, bp1.y };
            #pragma unroll
            for (int r = 0; r < 8; r++)
                #pragma unroll
                for (int j = 0; j < 4; j++)
                    ffma2(acc[r][j], ar[r], bp[j]);
        }

        if constexpr (FOLD) {
            // KC-panel boundary (mid-loop only; final fold after the loop)
            if ((((t + 1) << 4) % KC) == 0 && (t + 1) < nT) {
                #pragma unroll
                for (int r = 0; r < 8; r++)
                    #pragma unroll
                    for (int j = 0; j < 4; j++) {
                        fadd2(accT[r][j], acc[r][j]);
                        acc[r][j] = 0ull;
                    }
            }
        }

        if (more) {
            const int nxt = cur ^ 1;
            As2[nxt][lk+0][lr] = pk2(a0.x, a0.x);
            As2[nxt][lk+1][lr] = pk2(a0.y, a0.y);
            As2[nxt][lk+2][lr] = pk2(a0.z, a0.z);
            As2[nxt][lk+3][lr] = pk2(a0.w, a0.w);
            As2[nxt][lk+4][lr] = pk2(a1.x, a1.x);
            As2[nxt][lk+5][lr] = pk2(a1.y, a1.y);
            As2[nxt][lk+6][lr] = pk2(a1.z, a1.z);
            As2[nxt][lk+7][lr] = pk2(a1.w, a1.w);
            Bs [nxt][lk+0][lr] = w0.x;
            Bs [nxt][lk+1][lr] = w0.y;
            Bs [nxt][lk+2][lr] = w0.z;
            Bs [nxt][lk+3][lr] = w0.w;
            Bs [nxt][lk+4][lr] = w1.x;
            Bs [nxt][lk+5][lr] = w1.y;
            Bs [nxt][lk+6][lr] = w1.z;
            Bs [nxt][lk+7][lr] = w1.w;
        }
    }

    if constexpr (FOLD) {
        // final fold: C = rn(S0 + S1)
        #pragma unroll
        for (int r = 0; r < 8; r++)
            #pragma unroll
            for (int j = 0; j < 4; j++)
                fadd2(accT[r][j], acc[r][j]);
    }

    // ---- epilogue ----
    // thread covers rows bm+rowb+{0..7}, cols bn+colb+{0..7} (contiguous 8)
    const int col0 = bn + colb;
    float4 bb0 = *(const float4*)(bias + col0);
    float4 bb1 = *(const float4*)(bias + col0 + 4);

    #pragma unroll
    for (int r = 0; r < 8; r++) {
        const int row = bm + rowb + r;
        float2 p0, p1, p2, p3;
        if constexpr (FOLD) {
            p0 = upk2(accT[r][0]); p1 = upk2(accT[r][1]);
            p2 = upk2(accT[r][2]); p3 = upk2(accT[r][3]);
        } else {
            p0 = upk2(acc[r][0]);  p1 = upk2(acc[r][1]);
            p2 = upk2(acc[r][2]);  p3 = upk2(acc[r][3]);
        }

        // bias as separately rounded add (matches x@W.T + b)
        float4 cur0 = make_float4(__fadd_rn(p0.x, bb0.x), __fadd_rn(p0.y, bb0.y),
                                  __fadd_rn(p1.x, bb0.z), __fadd_rn(p1.y, bb0.w));
        float4 cur1 = make_float4(__fadd_rn(p2.x, bb1.x), __fadd_rn(p2.y, bb1.y),
                                  __fadd_rn(p3.x, bb1.z), __fadd_rn(p3.y, bb1.w));

        size_t i0 = (size_t)row * N + col0;
        size_t i1 = i0 + 4;

        if constexpr (MODE == 0) {
            *(float4*)(Ccur + i0) = cur0;
            *(float4*)(Ccur + i1) = cur1;
        } else {
            float4 m0 = *(const float4*)(Mst + i0);
            float4 m1 = *(const float4*)(Mst + i1);
            float4 s0, s1;
            lif_step(m0.x, cur0.x, s0.x); lif_step(m0.y, cur0.y, s0.y);
            lif_step(m0.z, cur0.z, s0.z); lif_step(m0.w, cur0.w, s0.w);
            lif_step(m1.x, cur1.x, s1.x); lif_step(m1.y, cur1.y, s1.y);
            lif_step(m1.z, cur1.z, s1.z); lif_step(m1.w, cur1.w, s1.w);
            *(float4*)(Mst + i0) = m0;
            *(float4*)(Mst + i1) = m1;
            if constexpr (MODE == 1) {
                *(float4*)(Sout + i0) = s0;
                *(float4*)(Sout + i1) = s1;
            } else {
                float4 o0 = *(const float4*)(Oacc + i0);
                float4 o1 = *(const float4*)(Oacc + i1);
                o0.x = __fmul_rn(__fadd_rn(o0.x, s0.x), outScale);
                o0.y = __fmul_rn(__fadd_rn(o0.y, s0.y), outScale);
                o0.z = __fmul_rn(__fadd_rn(o0.z, s0.z), outScale);
                o0.w = __fmul_rn(__fadd_rn(o0.w, s0.w), outScale);
                o1.x = __fmul_rn(__fadd_rn(o1.x, s1.x), outScale);
                o1.y = __fmul_rn(__fadd_rn(o1.y, s1.y), outScale);
                o1.z = __fmul_rn(__fadd_rn(o1.z, s1.z), outScale);
                o1.w = __fmul_rn(__fadd_rn(o1.w, s1.w), outScale);
                *(float4*)(Oacc + i0) = o0;
                *(float4*)(Oacc + i1) = o1;
            }
        }
    }
}

// elementwise LIF for layer 1 (cur1 is precomputed and constant over steps)
__global__ void lif1_kernel(const float* __restrict__ cur,
                            float* __restrict__ Mst,
                            float* __restrict__ S, int n4)
{
    int i = blockIdx.x * blockDim.x + threadIdx.x;
    if (i >= n4) return;
    float4 c = ((const float4*)cur)[i];
    float4 m = ((const float4*)Mst)[i];
    float4 s;
    lif_step(m.x, c.x, s.x);
    lif_step(m.y, c.y, s.y);
    lif_step(m.z, c.z, s.z);
    lif_step(m.w, c.w, s.w);
    ((float4*)Mst)[i] = m;
    ((float4*)S)[i]   = s;
}

// zero membranes + output (d_out arrives poisoned)
__global__ void init_kernel(float* __restrict__ out, int nBH4, int nBD4)
{
    int i = blockIdx.x * blockDim.x + threadIdx.x;
    float4 z = make_float4(0.f, 0.f, 0.f, 0.f);
    if (i < nBD4) {
        ((float4*)out)[i]  = z;
        ((float4*)g_m3)[i] = z;
    }
    if (i < nBH4) {
        ((float4*)g_m1)[i] = z;
        ((float4*)g_m2)[i] = z;
    }
}

extern "C" void kernel_launch(void* const* d_in, const int* in_sizes, int n_in,
                              void* d_out, int out_size)
{
    const float* x  = (const float*)d_in[0];
    const float* W1 = (const float*)d_in[1];
    const float* b1 = (const float*)d_in[2];
    const float* W2 = (const float*)d_in[3];
    const float* b2 = (const float*)d_in[4];
    const float* W3 = (const float*)d_in[5];
    const float* b3 = (const float*)d_in[6];

    const int H = in_sizes[2];          // 512
    const int D = in_sizes[6];          // 1024
    const int B = in_sizes[0] / D;      // 16384
    float* out = (float*)d_out;

    float *cur1, *m1, *m2, *m3, *s1, *s2;
    cudaGetSymbolAddress((void**)&cur1, g_cur1);
    cudaGetSymbolAddress((void**)&m1,   g_m1);
    cudaGetSymbolAddress((void**)&m2,   g_m2);
    cudaGetSymbolAddress((void**)&m3,   g_m3);
    cudaGetSymbolAddress((void**)&s1,   g_s1);
    cudaGetSymbolAddress((void**)&s2,   g_s2);

    const int nBH4 = (B * H) / 4;
    const int nBD4 = (B * D) / 4;

    init_kernel<<<(nBD4 + 255) / 256, 256>>>(out, nBH4, nBD4);

    // fc1(x): K=1024 -> KC=512 fold; constant over timesteps
    gemm_lif<0, true><<<dim3(H / 128, B / 128), 256>>>(
        x, W1, b1, cur1, nullptr, nullptr, nullptr, 1.0f, B, H, D);

    for (int t = 0; t < T_STEPS; t++) {
        lif1_kernel<<<(nBH4 + 255) / 256, 256>>>(cur1, m1, s1, nBH4);

        gemm_lif<1, false><<<dim3(H / 128, B / 128), 256>>>(
            s1, W2, b2, nullptr, m2, s2, nullptr, 1.0f, B, H, H);

        float sc = (t == T_STEPS - 1) ? (1.0f / (float)T_STEPS) : 1.0f;
        gemm_lif<2, false><<<dim3(D / 128, B / 128), 256>>>(
            s2, W3, b3, nullptr, m3, nullptr, out, sc, B, D, H);
    }
}

// round 17
// speedup vs baseline: 1.2065x; 1.2065x over previous
#include <cuda_runtime.h>

typedef unsigned long long u64;

#define BETA 0.95f
#define THRV 1.0f
#define KC   512              // fc1: two 512-halves folded; K=512 stays pure chain

static const int T_STEPS = 10;
static const int MAXB = 16384, MAXH = 512, MAXD = 1024;

// ---- persistent state (device globals; no runtime allocation allowed) ----
__device__ float g_cur1[MAXB * MAXH];   // fc1(x), computed once per launch
__device__ float g_m1[MAXB * MAXH];
__device__ float g_m2[MAXB * MAXH];
__device__ float g_m3[MAXB * MAXD];
__device__ float g_s1[MAXB * MAXH];
__device__ float g_s2[MAXB * MAXH];

// ---- f32x2 packed math (lane-wise identical rounding to scalar ops) ----
__device__ __forceinline__ float2 upk2(u64 v) {
    float2 f;
    asm("mov.b64 {%0, %1}, %2;" : "=f"(f.x), "=f"(f.y) : "l"(v));
    return f;
}
__device__ __forceinline__ u64 pk2(float x, float y) {
    u64 r;
    asm("mov.b64 %0, {%1, %2};" : "=l"(r) : "f"(x), "f"(y));
    return r;
}
__device__ __forceinline__ void ffma2(u64& d, u64 a, u64 b) {
    asm("fma.rn.f32x2 %0, %1, %2, %0;" : "+l"(d) : "l"(a), "l"(b));
}
__device__ __forceinline__ void fadd2(u64& d, u64 a) {
    asm("add.rn.f32x2 %0, %0, %1;" : "+l"(d) : "l"(a));
}

// LIF update, NO FMA contraction: m' = rn(rn(rn(beta*m) + cur) - reset)
__device__ __forceinline__ void lif_step(float& m, float cur, float& s) {
    float reset = (m > THRV) ? THRV : 0.0f;   // reset uses PREVIOUS mem
    float t0 = __fmul_rn(BETA, m);
    float t1 = __fadd_rn(t0, cur);
    m = __fsub_rn(t1, reset);
    s = (m > THRV) ? 1.0f : 0.0f;
}

// ============================================================================
// Fused GEMM:  C[M,N] = A[M,K] @ W[N,K]^T (+bias) -> epilogue per MODE
//   MODE 0: write cur     MODE 1: LIF -> Mst,Sout    MODE 2: LIF -> Oacc
// Tile BM=128, BN=128, BK=16, 256 threads.
// Warp grid 4(m) x 2(n): warp covers 32 rows x 64 cols (512B unique/warp-k).
// CONFLICT-FREE fragments:
//   A: rowb = 32*warp_m + 8*ty, ty = lane>>3 -> each 8-lane phase broadcasts
//      one address (1 bank-group per phase).
//   B: two DENSE 16B chunks per thread: cols {4tx..4tx+3} and {32+4tx..+3},
//      tx = lane&7 -> each phase reads 128B contiguous = all 32 banks once.
// Per-thread 8 rows x 8 cols as 4 f32x2 col-pair lanes; each lane is bitwise
// an ascending-k scalar FMA chain; KC=512 fold (FOLD) reproduces reference.
// Double-buffered smem (exactly 48KB), ONE __syncthreads per 16-k stage.
// ============================================================================
template<int MODE, bool FOLD>
__global__ __launch_bounds__(256, FOLD ? 1 : 2)
void gemm_lif(const float* __restrict__ A, const float* __restrict__ W,
              const float* __restrict__ bias,
              float* __restrict__ Ccur,
              float* __restrict__ Mst,
              float* __restrict__ Sout,
              float* __restrict__ Oacc,
              float outScale,
              int M, int N, int K)
{
    __shared__ __align__(16) u64   As2[2][16][128];  // [buf][k][row] = (a,a) dup
    __shared__ __align__(16) float Bs [2][16][128];  // [buf][k][col]

    const int tid    = threadIdx.x;
    const int lane   = tid & 31;
    const int wid    = tid >> 5;
    const int warp_m = wid & 3;        // 0..3 -> 32-row band
    const int warp_n = wid >> 2;       // 0..1 -> 64-col band
    const int tx     = lane & 7;       // dense col chunks at 4*tx and 32+4*tx
    const int ty     = lane >> 3;      // 0..3 -> 8-row group (phase-aligned)

    const int rowb = 32 * warp_m + 8 * ty;       // smem row base (u64 index)
    const int colb = 64 * warp_n + 4 * tx;       // smem col base (dense chunk)

    const int bm = blockIdx.y * 128;
    const int bn = blockIdx.x * 128;

    const int lr = tid >> 1;          // 0..127 (one A row / one B col)
    const int lk = (tid & 1) << 3;    // 0 or 8

    const float* Ag = A + (size_t)(bm + lr) * K + lk;
    const float* Wg = W + (size_t)(bn + lr) * K + lk;

    u64 acc[8][4];                    // [row r][colpair jp]
    u64 accT[8][4];                   // folded total (FOLD only)
    #pragma unroll
    for (int r = 0; r < 8; r++)
        #pragma unroll
        for (int j = 0; j < 4; j++) { acc[r][j] = 0ull; accT[r][j] = 0ull; }

    // prefetch + store stage 0
    float4 a0 = *(const float4*)(Ag + 0);
    float4 a1 = *(const float4*)(Ag + 4);
    float4 w0 = *(const float4*)(Wg + 0);
    float4 w1 = *(const float4*)(Wg + 4);
    {
        As2[0][lk+0][lr] = pk2(a0.x, a0.x);
        As2[0][lk+1][lr] = pk2(a0.y, a0.y);
        As2[0][lk+2][lr] = pk2(a0.z, a0.z);
        As2[0][lk+3][lr] = pk2(a0.w, a0.w);
        As2[0][lk+4][lr] = pk2(a1.x, a1.x);
        As2[0][lk+5][lr] = pk2(a1.y, a1.y);
        As2[0][lk+6][lr] = pk2(a1.z, a1.z);
        As2[0][lk+7][lr] = pk2(a1.w, a1.w);
        Bs [0][lk+0][lr] = w0.x;
        Bs [0][lk+1][lr] = w0.y;
        Bs [0][lk+2][lr] = w0.z;
        Bs [0][lk+3][lr] = w0.w;
        Bs [0][lk+4][lr] = w1.x;
        Bs [0][lk+5][lr] = w1.y;
        Bs [0][lk+6][lr] = w1.z;
        Bs [0][lk+7][lr] = w1.w;
    }

    const int nT = K >> 4;
    for (int t = 0; t < nT; t++) {
        const int cur = t & 1;
        __syncthreads();              // stage t visible; stage t-1 compute done

        const bool more = (t + 1 < nT);
        if (more) {
            const float* Ap = Ag + (t + 1) * 16;
            const float* Wp = Wg + (t + 1) * 16;
            a0 = *(const float4*)(Ap + 0);
            a1 = *(const float4*)(Ap + 4);
            w0 = *(const float4*)(Wp + 0);
            w1 = *(const float4*)(Wp + 4);
        }

        #pragma unroll
        for (int k = 0; k < 16; k++) {
            ulonglong2 ap0 = *(const ulonglong2*)&As2[cur][k][rowb + 0];
            ulonglong2 ap1 = *(const ulonglong2*)&As2[cur][k][rowb + 2];
            ulonglong2 ap2 = *(const ulonglong2*)&As2[cur][k][rowb + 4];
            ulonglong2 ap3 = *(const ulonglong2*)&As2[cur][k][rowb + 6];
            u64 ar[8] = { ap0.x, ap0.y, ap1.x, ap1.y,
                          ap2.x, ap2.y, ap3.x, ap3.y };
            ulonglong2 bp0 = *(const ulonglong2*)&Bs[cur][k][colb];       // cols 4tx..+3
            ulonglong2 bp1 = *(const ulonglong2*)&Bs[cur][k][colb + 32];  // cols 32+4tx..+3
            u64 bp[4] = { bp0.x, bp0.y, bp1.x, bp1.y };
            #pragma unroll
            for (int r = 0; r < 8; r++)
                #pragma unroll
                for (int j = 0; j < 4; j++)
                    ffma2(acc[r][j], ar[r], bp[j]);
        }

        if constexpr (FOLD) {
            // KC-panel boundary (mid-loop only; final fold after the loop)
            if ((((t + 1) << 4) % KC) == 0 && (t + 1) < nT) {
                #pragma unroll
                for (int r = 0; r < 8; r++)
                    #pragma unroll
                    for (int j = 0; j < 4; j++) {
                        fadd2(accT[r][j], acc[r][j]);
                        acc[r][j] = 0ull;
                    }
            }
        }

        if (more) {
            const int nxt = cur ^ 1;
            As2[nxt][lk+0][lr] = pk2(a0.x, a0.x);
            As2[nxt][lk+1][lr] = pk2(a0.y, a0.y);
            As2[nxt][lk+2][lr] = pk2(a0.z, a0.z);
            As2[nxt][lk+3][lr] = pk2(a0.w, a0.w);
            As2[nxt][lk+4][lr] = pk2(a1.x, a1.x);
            As2[nxt][lk+5][lr] = pk2(a1.y, a1.y);
            As2[nxt][lk+6][lr] = pk2(a1.z, a1.z);
            As2[nxt][lk+7][lr] = pk2(a1.w, a1.w);
            Bs [nxt][lk+0][lr] = w0.x;
            Bs [nxt][lk+1][lr] = w0.y;
            Bs [nxt][lk+2][lr] = w0.z;
            Bs [nxt][lk+3][lr] = w0.w;
            Bs [nxt][lk+4][lr] = w1.x;
            Bs [nxt][lk+5][lr] = w1.y;
            Bs [nxt][lk+6][lr] = w1.z;
            Bs [nxt][lk+7][lr] = w1.w;
        }
    }

    if constexpr (FOLD) {
        // final fold: C = rn(S0 + S1)
        #pragma unroll
        for (int r = 0; r < 8; r++)
            #pragma unroll
            for (int j = 0; j < 4; j++)
                fadd2(accT[r][j], acc[r][j]);
    }

    // ---- epilogue ----
    // thread covers rows bm+rowb+{0..7}, cols bn+colb+{0..3} and +32..+35
    const int col0 = bn + colb;
    float4 bb0 = *(const float4*)(bias + col0);
    float4 bb1 = *(const float4*)(bias + col0 + 32);

    #pragma unroll
    for (int r = 0; r < 8; r++) {
        const int row = bm + rowb + r;
        float2 p0, p1, p2, p3;
        if constexpr (FOLD) {
            p0 = upk2(accT[r][0]); p1 = upk2(accT[r][1]);
            p2 = upk2(accT[r][2]); p3 = upk2(accT[r][3]);
        } else {
            p0 = upk2(acc[r][0]);  p1 = upk2(acc[r][1]);
            p2 = upk2(acc[r][2]);  p3 = upk2(acc[r][3]);
        }

        // bias as separately rounded add (matches x@W.T + b)
        float4 cur0 = make_float4(__fadd_rn(p0.x, bb0.x), __fadd_rn(p0.y, bb0.y),
                                  __fadd_rn(p1.x, bb0.z), __fadd_rn(p1.y, bb0.w));
        float4 cur1 = make_float4(__fadd_rn(p2.x, bb1.x), __fadd_rn(p2.y, bb1.y),
                                  __fadd_rn(p3.x, bb1.z), __fadd_rn(p3.y, bb1.w));

        size_t i0 = (size_t)row * N + col0;
        size_t i1 = i0 + 32;

        if constexpr (MODE == 0) {
            *(float4*)(Ccur + i0) = cur0;
            *(float4*)(Ccur + i1) = cur1;
        } else {
            float4 m0 = *(const float4*)(Mst + i0);
            float4 m1 = *(const float4*)(Mst + i1);
            float4 s0, s1;
            lif_step(m0.x, cur0.x, s0.x); lif_step(m0.y, cur0.y, s0.y);
            lif_step(m0.z, cur0.z, s0.z); lif_step(m0.w, cur0.w, s0.w);
            lif_step(m1.x, cur1.x, s1.x); lif_step(m1.y, cur1.y, s1.y);
            lif_step(m1.z, cur1.z, s1.z); lif_step(m1.w, cur1.w, s1.w);
            *(float4*)(Mst + i0) = m0;
            *(float4*)(Mst + i1) = m1;
            if constexpr (MODE == 1) {
                *(float4*)(Sout + i0) = s0;
                *(float4*)(Sout + i1) = s1;
            } else {
                float4 o0 = *(const float4*)(Oacc + i0);
                float4 o1 = *(const float4*)(Oacc + i1);
                o0.x = __fmul_rn(__fadd_rn(o0.x, s0.x), outScale);
                o0.y = __fmul_rn(__fadd_rn(o0.y, s0.y), outScale);
                o0.z = __fmul_rn(__fadd_rn(o0.z, s0.z), outScale);
                o0.w = __fmul_rn(__fadd_rn(o0.w, s0.w), outScale);
                o1.x = __fmul_rn(__fadd_rn(o1.x, s1.x), outScale);
                o1.y = __fmul_rn(__fadd_rn(o1.y, s1.y), outScale);
                o1.z = __fmul_rn(__fadd_rn(o1.z, s1.z), outScale);
                o1.w = __fmul_rn(__fadd_rn(o1.w, s1.w), outScale);
                *(float4*)(Oacc + i0) = o0;
                *(float4*)(Oacc + i1) = o1;
            }
        }
    }
}

// elementwise LIF for layer 1 (cur1 is precomputed and constant over steps)
__global__ void lif1_kernel(const float* __restrict__ cur,
                            float* __restrict__ Mst,
                            float* __restrict__ S, int n4)
{
    int i = blockIdx.x * blockDim.x + threadIdx.x;
    if (i >= n4) return;
    float4 c = ((const float4*)cur)[i];
    float4 m = ((const float4*)Mst)[i];
    float4 s;
    lif_step(m.x, c.x, s.x);
    lif_step(m.y, c.y, s.y);
    lif_step(m.z, c.z, s.z);
    lif_step(m.w, c.w, s.w);
    ((float4*)Mst)[i] = m;
    ((float4*)S)[i]   = s;
}

// zero membranes + output (d_out arrives poisoned)
__global__ void init_kernel(float* __restrict__ out, int nBH4, int nBD4)
{
    int i = blockIdx.x * blockDim.x + threadIdx.x;
    float4 z = make_float4(0.f, 0.f, 0.f, 0.f);
    if (i < nBD4) {
        ((float4*)out)[i]  = z;
        ((float4*)g_m3)[i] = z;
    }
    if (i < nBH4) {
        ((float4*)g_m1)[i] = z;
        ((float4*)g_m2)[i] = z;
    }
}

extern "C" void kernel_launch(void* const* d_in, const int* in_sizes, int n_in,
                              void* d_out, int out_size)
{
    const float* x  = (const float*)d_in[0];
    const float* W1 = (const float*)d_in[1];
    const float* b1 = (const float*)d_in[2];
    const float* W2 = (const float*)d_in[3];
    const float* b2 = (const float*)d_in[4];
    const float* W3 = (const float*)d_in[5];
    const float* b3 = (const float*)d_in[6];

    const int H = in_sizes[2];          // 512
    const int D = in_sizes[6];          // 1024
    const int B = in_sizes[0] / D;      // 16384
    float* out = (float*)d_out;

    float *cur1, *m1, *m2, *m3, *s1, *s2;
    cudaGetSymbolAddress((void**)&cur1, g_cur1);
    cudaGetSymbolAddress((void**)&m1,   g_m1);
    cudaGetSymbolAddress((void**)&m2,   g_m2);
    cudaGetSymbolAddress((void**)&m3,   g_m3);
    cudaGetSymbolAddress((void**)&s1,   g_s1);
    cudaGetSymbolAddress((void**)&s2,   g_s2);

    const int nBH4 = (B * H) / 4;
    const int nBD4 = (B * D) / 4;

    init_kernel<<<(nBD4 + 255) / 256, 256>>>(out, nBH4, nBD4);

    // fc1(x): K=1024 -> KC=512 fold; constant over timesteps
    gemm_lif<0, true><<<dim3(H / 128, B / 128), 256>>>(
        x, W1, b1, cur1, nullptr, nullptr, nullptr, 1.0f, B, H, D);

    for (int t = 0; t < T_STEPS; t++) {
        lif1_kernel<<<(nBH4 + 255) / 256, 256>>>(cur1, m1, s1, nBH4);

        gemm_lif<1, false><<<dim3(H / 128, B / 128), 256>>>(
            s1, W2, b2, nullptr, m2, s2, nullptr, 1.0f, B, H, H);

        float sc = (t == T_STEPS - 1) ? (1.0f / (float)T_STEPS) : 1.0f;
        gemm_lif<2, false><<<dim3(D / 128, B / 128), 256>>>(
            s2, W3, b3, nullptr, m3, nullptr, out, sc, B, D, H);
    }
}